// round 11
// baseline (speedup 1.0000x reference)
#include <cuda_runtime.h>
#include <cuda_bf16.h>
#include <stdint.h>

#define NNODES 8192
#define DIM    256
#define ALPHA  3.0f
#define NEG    0.2f

#define TPB   256                // softmax threads per block (proven)
#define CPT   (NNODES / TPB)     // 32 columns per thread
#define VEC4  (CPT / 4)          // 8 float4 groups per thread
#define NBLK  444                // persistent blocks: 3 per SM x 148 SMs

// Scratch (__device__ globals; no cudaMalloc allowed)
__device__ float g_s1[NNODES];
__device__ float g_s2p[NNODES];  // permuted: g_s2p[idx[j]] = s2[j]

// Single-op hardware tanh (sm_75+): MUFU.TANH, rel err ~2^-11 (<< 1e-3 budget)
__device__ __forceinline__ float htanh(float x) {
    float y;
    asm("tanh.approx.f32 %0, %1;" : "=f"(y) : "f"(x));
    return y;
}

// ---------------------------------------------------------------------------
// score: HALF-WARP per node (16 lanes x 16 dims each) — unchanged from R9.
// ---------------------------------------------------------------------------
__global__ void __launch_bounds__(128)
score_kernel(const int* __restrict__ idx,
             const float* __restrict__ e1,
             const float* __restrict__ e2,
             const float* __restrict__ w)
{
    const int node = (blockIdx.x * 128 + threadIdx.x) >> 4;
    const int sub  = threadIdx.x & 15;
    const int src  = __ldg(&idx[node]);

    const float4* r1 = (const float4*)(e1 + (size_t)src * DIM);
    const float4* r2 = (const float4*)(e2 + (size_t)src * DIM);
    const float4* w1 = (const float4*)(w);
    const float4* w2 = (const float4*)(w + DIM);

    float p1 = 0.f, p2 = 0.f;
    #pragma unroll
    for (int q = 0; q < 4; q++) {
        const int k = sub + 16 * q;                 // interleaved -> coalesced
        float4 a  = r1[k];
        float4 b  = r2[k];
        float4 wa = __ldg(&w1[k]);
        float4 wb = __ldg(&w2[k]);
        p1 += htanh(ALPHA * a.x) * wa.x + htanh(ALPHA * a.y) * wa.y
            + htanh(ALPHA * a.z) * wa.z + htanh(ALPHA * a.w) * wa.w;
        p2 += htanh(ALPHA * b.x) * wb.x + htanh(ALPHA * b.y) * wb.y
            + htanh(ALPHA * b.z) * wb.z + htanh(ALPHA * b.w) * wb.w;
    }
    #pragma unroll
    for (int o = 8; o > 0; o >>= 1) {
        p1 += __shfl_xor_sync(0xffffffffu, p1, o);
        p2 += __shfl_xor_sync(0xffffffffu, p2, o);
    }
    if (sub == 0) {
        g_s1[node] = p1;
        g_s2p[src] = p2;
    }
}

// ---------------------------------------------------------------------------
// softmax: PERSISTENT blocks. Each thread loads its 32-value s2 slice into
// REGISTERS once, then grid-strides over rows. Per row: pass 1 = exp+sum
// (exp is throughput-trivial), block reduce, pass 2 = exp*inv + float4 store.
// No per-row s2p L1 traffic, no vals[] cache, no per-row block setup.
// ---------------------------------------------------------------------------
__global__ void __launch_bounds__(TPB)
softmax_kernel(const float* __restrict__ att_b,
               float* __restrict__ out)
{
    const int t = threadIdx.x;
    const float bias = att_b[0];

    // load s2 slice into registers once per block
    float s2c[CPT];
    {
        const float4* s2p4 = (const float4*)g_s2p;
        #pragma unroll
        for (int q = 0; q < VEC4; q++) {
            float4 s = __ldg(&s2p4[q * TPB + t]);
            s2c[q * 4 + 0] = s.x;
            s2c[q * 4 + 1] = s.y;
            s2c[q * 4 + 2] = s.z;
            s2c[q * 4 + 3] = s.w;
        }
    }

    __shared__ float shs[TPB / 32];

    for (int i = blockIdx.x; i < NNODES; i += NBLK) {
        const float base = g_s1[i] + bias;

        // pass 1: row sum of exp(leaky(base + s2))
        float sum = 0.f;
        #pragma unroll
        for (int k = 0; k < CPT; k++) {
            float x = base + s2c[k];
            x = (x > 0.f) ? x : NEG * x;
            sum += __expf(x);
        }
        #pragma unroll
        for (int o = 16; o > 0; o >>= 1)
            sum += __shfl_xor_sync(0xffffffffu, sum, o);
        if ((t & 31) == 0) shs[t >> 5] = sum;
        __syncthreads();
        sum = 0.f;
        #pragma unroll
        for (int wgi = 0; wgi < TPB / 32; wgi++) sum += shs[wgi];
        const float inv = __frcp_rn(sum);
        __syncthreads();   // protect shs before next row overwrites

        // pass 2: recompute exp, scale, contiguous float4 stores
        float4* row4 = (float4*)(out + (size_t)i * NNODES);
        #pragma unroll
        for (int q = 0; q < VEC4; q++) {
            float4 v;
            #pragma unroll
            for (int u = 0; u < 4; u++) {
                float x = base + s2c[q * 4 + u];
                x = (x > 0.f) ? x : NEG * x;
                ((float*)&v)[u] = __expf(x) * inv;
            }
            row4[q * TPB + t] = v;
        }
    }
}

// ---------------------------------------------------------------------------
// Inputs: idx[int32 N], emb1_w[f32 N*D], emb2_w[f32 N*D], att_w[f32 2D],
//         att_b[f32 1].  Output: f32 N*N.
// ---------------------------------------------------------------------------
extern "C" void kernel_launch(void* const* d_in, const int* in_sizes, int n_in,
                              void* d_out, int out_size)
{
    const int*   idx  = (const int*)  d_in[0];
    const float* e1   = (const float*)d_in[1];
    const float* e2   = (const float*)d_in[2];
    const float* attw = (const float*)d_in[3];
    const float* attb = (const float*)d_in[4];
    float*       out  = (float*)d_out;

    score_kernel<<<NNODES * 16 / 128, 128>>>(idx, e1, e2, attw);
    softmax_kernel<<<NBLK, TPB>>>(attb, out);
}